// round 1
// baseline (speedup 1.0000x reference)
#include <cuda_runtime.h>
#include <cstdint>

#define D 256
#define RT 16   // relations per block in k_rel

// Scratch (no cudaMalloc allowed): sub vector, precomputed input-gate vector, per-relation obj table.
__device__ float g_sub[D];
__device__ float g_gi[3 * D];
__device__ float g_obj[2048 * D];   // supports up to R=2048 relations (problem has R=1000)

__device__ __forceinline__ float sigmoidf_(float x) { return 1.0f / (1.0f + expf(-x)); }

// dot of a 256-float global row with a 256-float shared vector
__device__ __forceinline__ float dot256(const float* __restrict__ w, const float* s) {
    const float4* w4 = reinterpret_cast<const float4*>(w);
    const float4* s4 = reinterpret_cast<const float4*>(s);
    float acc = 0.0f;
#pragma unroll 16
    for (int k = 0; k < D / 4; k++) {
        float4 a = w4[k];
        float4 b = s4[k];
        acc += a.x * b.x + a.y * b.y + a.z * b.z + a.w * b.w;
    }
    return acc;
}

// ---------------------------------------------------------------------------
// Kernel 1: sub = tanh(mask @ sub_W^T + sub_b); r0 = GRU(enc, sub);
//           g_gi = r0 @ W_ih^T + b_ih  (shared by ALL edges since x is broadcast)
// One block, 256 threads.
// ---------------------------------------------------------------------------
__global__ void k_prolog(const float* __restrict__ enc, const float* __restrict__ mask,
                         const float* __restrict__ W_ih, const float* __restrict__ W_hh,
                         const float* __restrict__ b_ih, const float* __restrict__ b_hh,
                         const float* __restrict__ sub_W, const float* __restrict__ sub_b) {
    __shared__ float s_mask[D], s_enc[D], s_sub[D], s_r0[D];
    int t = threadIdx.x;
    s_mask[t] = mask[t];
    s_enc[t] = enc[t];
    __syncthreads();

    // sub = tanh(mask @ sub_W^T + sub_b)
    float sub = tanhf(dot256(sub_W + (size_t)t * D, s_mask) + sub_b[t]);
    s_sub[t] = sub;
    g_sub[t] = sub;
    __syncthreads();

    // r0 = GRUCell(x=enc, h=sub)
    float gi0[3], gh0[3];
#pragma unroll
    for (int g = 0; g < 3; g++) {
        int j = t + g * D;
        gi0[g] = dot256(W_ih + (size_t)j * D, s_enc) + b_ih[j];
        gh0[g] = dot256(W_hh + (size_t)j * D, s_sub) + b_hh[j];
    }
    float rg = sigmoidf_(gi0[0] + gh0[0]);
    float zg = sigmoidf_(gi0[1] + gh0[1]);
    float ng = tanhf(gi0[2] + rg * gh0[2]);
    float r0 = (1.0f - zg) * ng + zg * sub;
    s_r0[t] = r0;
    __syncthreads();

    // gi (for the edge-stage GRU) = r0 @ W_ih^T + b_ih
#pragma unroll
    for (int g = 0; g < 3; g++) {
        int j = t + g * D;
        g_gi[j] = dot256(W_ih + (size_t)j * D, s_r0) + b_ih[j];
    }
}

// ---------------------------------------------------------------------------
// Kernel 2: per-RELATION (not per-edge!) GRU + obj projection.
//   gh = rel_table @ W_hh^T + b_hh ; rj = gru_combine(g_gi, gh, rel_table)
//   g_obj[r] = tanh(rj @ obj_W^T + obj_b)
// Each block handles RT=16 relations with 256 threads; thread t owns output
// dim t of all three gates (rows t, t+256, t+512 of W_hh).
// ---------------------------------------------------------------------------
__global__ void k_rel(const float* __restrict__ rel_table, const float* __restrict__ W_hh,
                      const float* __restrict__ b_hh, const float* __restrict__ obj_W,
                      const float* __restrict__ obj_b, int R) {
    __shared__ float s_h[RT][D];
    __shared__ float s_rj[RT][D];
    int t = threadIdx.x;
    int rbase = blockIdx.x * RT;
    int nr = R - rbase;
    if (nr > RT) nr = RT;

#pragma unroll
    for (int r = 0; r < RT; r++)
        s_h[r][t] = (r < nr) ? rel_table[(size_t)(rbase + r) * D + t] : 0.0f;
    __syncthreads();

    float accR[RT], accZ[RT], accN[RT];
#pragma unroll
    for (int r = 0; r < RT; r++) { accR[r] = 0.f; accZ[r] = 0.f; accN[r] = 0.f; }

    const float4* wr = reinterpret_cast<const float4*>(W_hh + (size_t)t * D);
    const float4* wz = reinterpret_cast<const float4*>(W_hh + (size_t)(t + D) * D);
    const float4* wn = reinterpret_cast<const float4*>(W_hh + (size_t)(t + 2 * D) * D);
    for (int k = 0; k < D / 4; k++) {
        float4 vr = wr[k], vz = wz[k], vn = wn[k];
#pragma unroll
        for (int r = 0; r < RT; r++) {
            float4 h4 = reinterpret_cast<const float4*>(s_h[r])[k];
            accR[r] += vr.x * h4.x + vr.y * h4.y + vr.z * h4.z + vr.w * h4.w;
            accZ[r] += vz.x * h4.x + vz.y * h4.y + vz.z * h4.z + vz.w * h4.w;
            accN[r] += vn.x * h4.x + vn.y * h4.y + vn.z * h4.z + vn.w * h4.w;
        }
    }

    float ir = g_gi[t], iz = g_gi[D + t], in_ = g_gi[2 * D + t];
    float bhr = b_hh[t], bhz = b_hh[D + t], bhn = b_hh[2 * D + t];
#pragma unroll
    for (int r = 0; r < RT; r++) {
        float rg = sigmoidf_(ir + accR[r] + bhr);
        float zg = sigmoidf_(iz + accZ[r] + bhz);
        float ng = tanhf(in_ + rg * (accN[r] + bhn));
        s_rj[r][t] = (1.0f - zg) * ng + zg * s_h[r][t];
    }
    __syncthreads();

    float accO[RT];
#pragma unroll
    for (int r = 0; r < RT; r++) accO[r] = 0.f;
    const float4* wo = reinterpret_cast<const float4*>(obj_W + (size_t)t * D);
    for (int k = 0; k < D / 4; k++) {
        float4 v = wo[k];
#pragma unroll
        for (int r = 0; r < RT; r++) {
            float4 h4 = reinterpret_cast<const float4*>(s_rj[r])[k];
            accO[r] += v.x * h4.x + v.y * h4.y + v.z * h4.z + v.w * h4.w;
        }
    }
    float ob = obj_b[t];
#pragma unroll
    for (int r = 0; r < RT; r++) {
        if (r < nr) g_obj[(size_t)(rbase + r) * D + t] = tanhf(accO[r] + ob);
    }
}

// ---------------------------------------------------------------------------
// Kernel 3a: seed row (written BEFORE the tail scatter, matching reference
// override order ent.at[seed].set then ent.at[tail_ids].set).
// ---------------------------------------------------------------------------
__global__ void k_seed(const int* __restrict__ seed_p, float* __restrict__ out) {
    int t = threadIdx.x;
    int seed = *seed_p;  // first 4 LE bytes valid for int32 or int64 scalar
    out[(size_t)seed * D + t] = g_sub[t];
}

// ---------------------------------------------------------------------------
// Kernel 3b: the HBM-bound scatter. 64 threads (16 float4s... no: 64 float4s,
// one per thread) per row, 4 rows per 256-thread block.
// ent[tail_ids[e]] = state==1 ? entity_table[origin_ids[e]] : g_obj[rel_ids[e]]
// ---------------------------------------------------------------------------
__global__ void k_scatter(const float* __restrict__ ent_table, const int* __restrict__ rel_ids,
                          const int* __restrict__ tail_ids, const int* __restrict__ tails_state,
                          const int* __restrict__ origin_ids, float* __restrict__ out, int E) {
    int row = blockIdx.x * 4 + (threadIdx.x >> 6);
    int lane = threadIdx.x & 63;
    if (row >= E) return;
    int st = tails_state[row];
    const float4* src = (st == 1)
        ? reinterpret_cast<const float4*>(ent_table) + (size_t)origin_ids[row] * (D / 4)
        : reinterpret_cast<const float4*>(g_obj) + (size_t)rel_ids[row] * (D / 4);
    float4* dst = reinterpret_cast<float4*>(out) + (size_t)tail_ids[row] * (D / 4);
    dst[lane] = src[lane];
}

// ---------------------------------------------------------------------------
extern "C" void kernel_launch(void* const* d_in, const int* in_sizes, int n_in,
                              void* d_out, int out_size) {
    const float* enc       = (const float*)d_in[0];
    const float* mask      = (const float*)d_in[1];
    const float* ent_table = (const float*)d_in[2];
    const float* rel_table = (const float*)d_in[3];
    const float* W_ih      = (const float*)d_in[4];
    const float* W_hh      = (const float*)d_in[5];
    const float* b_ih      = (const float*)d_in[6];
    const float* b_hh      = (const float*)d_in[7];
    const float* sub_W     = (const float*)d_in[8];
    const float* sub_b     = (const float*)d_in[9];
    const float* obj_W     = (const float*)d_in[10];
    const float* obj_b     = (const float*)d_in[11];
    const int*   rel_ids   = (const int*)d_in[12];
    const int*   tail_ids  = (const int*)d_in[13];
    const int*   tails_st  = (const int*)d_in[14];
    const int*   origin    = (const int*)d_in[15];
    const int*   seed_p    = (const int*)d_in[16];
    float* out = (float*)d_out;

    int E = in_sizes[12];
    int R = in_sizes[3] / D;

    k_prolog<<<1, D>>>(enc, mask, W_ih, W_hh, b_ih, b_hh, sub_W, sub_b);
    k_rel<<<(R + RT - 1) / RT, D>>>(rel_table, W_hh, b_hh, obj_W, obj_b, R);
    k_seed<<<1, D>>>(seed_p, out);
    k_scatter<<<(E + 3) / 4, D>>>(ent_table, rel_ids, tail_ids, tails_st, origin, out, E);
}

// round 2
// speedup vs baseline: 2.4973x; 2.4973x over previous
#include <cuda_runtime.h>
#include <cstdint>

#define D 256
#define RT 8   // relations per block in k_rel

typedef unsigned long long u64;

// Scratch (no cudaMalloc allowed).
__device__ float g_sub[D];
__device__ float g_r0[D];
__device__ float g_gi[3 * D];
__device__ float g_obj[2048 * D];   // supports up to R=2048 relations (problem has R=1000)

__device__ __forceinline__ float sigmoidf_(float x) { return 1.0f / (1.0f + expf(-x)); }

__device__ __forceinline__ float wredsum(float v) {
#pragma unroll
    for (int o = 16; o; o >>= 1) v += __shfl_xor_sync(0xffffffffu, v, o);
    return v;
}

// packed f32x2 fma: acc = a*b + acc (lane-wise on 2 packed floats)
__device__ __forceinline__ void fma2(u64& acc, u64 a, u64 b) {
    asm("fma.rn.f32x2 %0, %1, %2, %3;" : "=l"(acc) : "l"(a), "l"(b), "l"(acc));
}
__device__ __forceinline__ float unpack_sum(u64 acc) {
    float lo = __uint_as_float((unsigned)(acc & 0xffffffffu));
    float hi = __uint_as_float((unsigned)(acc >> 32));
    return lo + hi;
}

// Coalesced warp dot: row-major W row j (256 floats) with vector x (256 floats).
// Lane l accumulates float4 elements l and l+32, then warp-reduce.
__device__ __forceinline__ float warp_dot256(const float* __restrict__ Wrow,
                                             const float* __restrict__ x, int lane) {
    const float4* w4 = reinterpret_cast<const float4*>(Wrow);
    const float4* x4 = reinterpret_cast<const float4*>(x);
    float4 a0 = w4[lane],      b0 = x4[lane];
    float4 a1 = w4[lane + 32], b1 = x4[lane + 32];
    float s = a0.x * b0.x + a0.y * b0.y + a0.z * b0.z + a0.w * b0.w
            + a1.x * b1.x + a1.y * b1.y + a1.z * b1.z + a1.w * b1.w;
    return wredsum(s);
}

// ---------------------------------------------------------------------------
// Prolog stage A: sub = tanh(sub_W @ mask + sub_b).  warp-per-output, 32x256.
// ---------------------------------------------------------------------------
__global__ void kA_sub(const float* __restrict__ mask, const float* __restrict__ sub_W,
                       const float* __restrict__ sub_b) {
    int lane = threadIdx.x & 31;
    int j = blockIdx.x * 8 + (threadIdx.x >> 5);
    float s = warp_dot256(sub_W + (size_t)j * D, mask, lane);
    if (lane == 0) g_sub[j] = tanhf(s + sub_b[j]);
}

// ---------------------------------------------------------------------------
// Prolog stage B: r0 = GRUCell(x=enc, h=sub).  warp-per-output j (6 dots each).
// ---------------------------------------------------------------------------
__global__ void kB_r0(const float* __restrict__ enc, const float* __restrict__ W_ih,
                      const float* __restrict__ W_hh, const float* __restrict__ b_ih,
                      const float* __restrict__ b_hh) {
    int lane = threadIdx.x & 31;
    int j = blockIdx.x * 8 + (threadIdx.x >> 5);
    float gi[3], gh[3];
#pragma unroll
    for (int g = 0; g < 3; g++) {
        int row = g * D + j;
        gi[g] = warp_dot256(W_ih + (size_t)row * D, enc, lane);
        gh[g] = warp_dot256(W_hh + (size_t)row * D, g_sub, lane);
    }
    if (lane == 0) {
        float rg = sigmoidf_(gi[0] + b_ih[j] + gh[0] + b_hh[j]);
        float zg = sigmoidf_(gi[1] + b_ih[D + j] + gh[1] + b_hh[D + j]);
        float ng = tanhf(gi[2] + b_ih[2 * D + j] + rg * (gh[2] + b_hh[2 * D + j]));
        float sub = g_sub[j];
        g_r0[j] = (1.0f - zg) * ng + zg * sub;
    }
}

// ---------------------------------------------------------------------------
// Prolog stage C: g_gi = W_ih @ r0 + b_ih  (768 outputs, shared by all edges).
// ---------------------------------------------------------------------------
__global__ void kC_gi(const float* __restrict__ W_ih, const float* __restrict__ b_ih) {
    int lane = threadIdx.x & 31;
    int j = blockIdx.x * 8 + (threadIdx.x >> 5);   // 0..767
    float s = warp_dot256(W_ih + (size_t)j * D, g_r0, lane);
    if (lane == 0) g_gi[j] = s + b_ih[j];
}

// ---------------------------------------------------------------------------
// Kernel 2: per-RELATION GRU + obj projection using packed f32x2 FMA.
// Block: 256 threads, RT=8 relations; thread t owns output dim t of 3 gates.
// ---------------------------------------------------------------------------
__global__ void k_rel(const float* __restrict__ rel_table, const float* __restrict__ W_hh,
                      const float* __restrict__ b_hh, const float* __restrict__ obj_W,
                      const float* __restrict__ obj_b, int R) {
    __shared__ float s_h[RT][D];
    __shared__ float s_rj[RT][D];
    int t = threadIdx.x;
    int rbase = blockIdx.x * RT;
    int nr = R - rbase;
    if (nr > RT) nr = RT;

#pragma unroll
    for (int r = 0; r < RT; r++)
        s_h[r][t] = (r < nr) ? rel_table[(size_t)(rbase + r) * D + t] : 0.0f;
    __syncthreads();

    u64 accR[RT], accZ[RT], accN[RT];
#pragma unroll
    for (int r = 0; r < RT; r++) { accR[r] = 0; accZ[r] = 0; accN[r] = 0; }

    const ulonglong2* wr = reinterpret_cast<const ulonglong2*>(W_hh + (size_t)t * D);
    const ulonglong2* wz = reinterpret_cast<const ulonglong2*>(W_hh + (size_t)(t + D) * D);
    const ulonglong2* wn = reinterpret_cast<const ulonglong2*>(W_hh + (size_t)(t + 2 * D) * D);
#pragma unroll 4
    for (int k = 0; k < D / 4; k++) {
        ulonglong2 vr = wr[k], vz = wz[k], vn = wn[k];
#pragma unroll
        for (int r = 0; r < RT; r++) {
            ulonglong2 h2 = reinterpret_cast<const ulonglong2*>(s_h[r])[k];
            fma2(accR[r], vr.x, h2.x); fma2(accR[r], vr.y, h2.y);
            fma2(accZ[r], vz.x, h2.x); fma2(accZ[r], vz.y, h2.y);
            fma2(accN[r], vn.x, h2.x); fma2(accN[r], vn.y, h2.y);
        }
    }

    float ir = g_gi[t], iz = g_gi[D + t], in_ = g_gi[2 * D + t];
    float bhr = b_hh[t], bhz = b_hh[D + t], bhn = b_hh[2 * D + t];
#pragma unroll
    for (int r = 0; r < RT; r++) {
        float rg = sigmoidf_(ir + unpack_sum(accR[r]) + bhr);
        float zg = sigmoidf_(iz + unpack_sum(accZ[r]) + bhz);
        float ng = tanhf(in_ + rg * (unpack_sum(accN[r]) + bhn));
        s_rj[r][t] = (1.0f - zg) * ng + zg * s_h[r][t];
    }
    __syncthreads();

    u64 accO[RT];
#pragma unroll
    for (int r = 0; r < RT; r++) accO[r] = 0;
    const ulonglong2* wo = reinterpret_cast<const ulonglong2*>(obj_W + (size_t)t * D);
#pragma unroll 4
    for (int k = 0; k < D / 4; k++) {
        ulonglong2 v = wo[k];
#pragma unroll
        for (int r = 0; r < RT; r++) {
            ulonglong2 h2 = reinterpret_cast<const ulonglong2*>(s_rj[r])[k];
            fma2(accO[r], v.x, h2.x); fma2(accO[r], v.y, h2.y);
        }
    }
    float ob = obj_b[t];
#pragma unroll
    for (int r = 0; r < RT; r++) {
        if (r < nr) g_obj[(size_t)(rbase + r) * D + t] = tanhf(unpack_sum(accO[r]) + ob);
    }
}

// ---------------------------------------------------------------------------
// Seed row (before tail scatter; tails override seed like the reference).
// ---------------------------------------------------------------------------
__global__ void k_seed(const int* __restrict__ seed_p, float* __restrict__ out) {
    int t = threadIdx.x;
    int seed = *seed_p;
    out[(size_t)seed * D + t] = g_sub[t];
}

// ---------------------------------------------------------------------------
// HBM-bound scatter, high MLP: each warp handles 4 rows, lane copies 2 float4
// per row; all 8 loads issued before any store.
// ent[tail_ids[e]] = state==1 ? entity_table[origin_ids[e]] : g_obj[rel_ids[e]]
// ---------------------------------------------------------------------------
__global__ void k_scatter(const float* __restrict__ ent_table, const int* __restrict__ rel_ids,
                          const int* __restrict__ tail_ids, const int* __restrict__ tails_state,
                          const int* __restrict__ origin_ids, float* __restrict__ out, int E) {
    int warp = threadIdx.x >> 5;
    int lane = threadIdx.x & 31;
    int base = (blockIdx.x * 8 + warp) * 4;

    float4 v[4][2];
    float4* dst[4];
    bool ok[4];
#pragma unroll
    for (int i = 0; i < 4; i++) {
        int row = base + i;
        ok[i] = row < E;
        if (ok[i]) {
            int st = tails_state[row];
            const float4* src = (st == 1)
                ? reinterpret_cast<const float4*>(ent_table) + (size_t)origin_ids[row] * (D / 4)
                : reinterpret_cast<const float4*>(g_obj) + (size_t)rel_ids[row] * (D / 4);
            dst[i] = reinterpret_cast<float4*>(out) + (size_t)tail_ids[row] * (D / 4);
            v[i][0] = src[lane];
            v[i][1] = src[lane + 32];
        }
    }
#pragma unroll
    for (int i = 0; i < 4; i++) {
        if (ok[i]) {
            dst[i][lane] = v[i][0];
            dst[i][lane + 32] = v[i][1];
        }
    }
}

// ---------------------------------------------------------------------------
extern "C" void kernel_launch(void* const* d_in, const int* in_sizes, int n_in,
                              void* d_out, int out_size) {
    const float* enc       = (const float*)d_in[0];
    const float* mask      = (const float*)d_in[1];
    const float* ent_table = (const float*)d_in[2];
    const float* rel_table = (const float*)d_in[3];
    const float* W_ih      = (const float*)d_in[4];
    const float* W_hh      = (const float*)d_in[5];
    const float* b_ih      = (const float*)d_in[6];
    const float* b_hh      = (const float*)d_in[7];
    const float* sub_W     = (const float*)d_in[8];
    const float* sub_b     = (const float*)d_in[9];
    const float* obj_W     = (const float*)d_in[10];
    const float* obj_b     = (const float*)d_in[11];
    const int*   rel_ids   = (const int*)d_in[12];
    const int*   tail_ids  = (const int*)d_in[13];
    const int*   tails_st  = (const int*)d_in[14];
    const int*   origin    = (const int*)d_in[15];
    const int*   seed_p    = (const int*)d_in[16];
    float* out = (float*)d_out;

    int E = in_sizes[12];
    int R = in_sizes[3] / D;

    kA_sub<<<32, 256>>>(mask, sub_W, sub_b);                       // 256 outputs, warp each
    kB_r0<<<32, 256>>>(enc, W_ih, W_hh, b_ih, b_hh);               // 256 outputs
    kC_gi<<<96, 256>>>(W_ih, b_ih);                                // 768 outputs
    k_rel<<<(R + RT - 1) / RT, 256>>>(rel_table, W_hh, b_hh, obj_W, obj_b, R);
    k_seed<<<1, D>>>(seed_p, out);
    k_scatter<<<(E + 31) / 32, 256>>>(ent_table, rel_ids, tail_ids, tails_st, origin, out, E);
}

// round 3
// speedup vs baseline: 2.7520x; 1.1020x over previous
#include <cuda_runtime.h>
#include <cstdint>

#define D 256
#define RT 8      // relations per block in k_rel
#define KT 32     // k-tile width staged in smem
#define PAD 36    // smem row stride (floats): 144B -> 16B aligned, conflict-free
#define NTILE (D / KT)

typedef unsigned long long u64;

// Scratch (no cudaMalloc allowed).
__device__ float g_sub[D];
__device__ float g_r0[D];
__device__ float g_gi[3 * D];
__device__ float g_obj[2048 * D];   // supports up to R=2048 relations (problem has R=1000)

__device__ __forceinline__ float sigmoidf_(float x) { return 1.0f / (1.0f + expf(-x)); }

__device__ __forceinline__ float wredsum(float v) {
#pragma unroll
    for (int o = 16; o; o >>= 1) v += __shfl_xor_sync(0xffffffffu, v, o);
    return v;
}

// packed f32x2 fma: acc = a*b + acc (lane-wise on 2 packed floats)
__device__ __forceinline__ void fma2(u64& acc, u64 a, u64 b) {
    asm("fma.rn.f32x2 %0, %1, %2, %3;" : "=l"(acc) : "l"(a), "l"(b), "l"(acc));
}
__device__ __forceinline__ float unpack_sum(u64 acc) {
    float lo = __uint_as_float((unsigned)(acc & 0xffffffffu));
    float hi = __uint_as_float((unsigned)(acc >> 32));
    return lo + hi;
}

// Coalesced warp dot: row-major W row (256 floats) with vector x.
__device__ __forceinline__ float warp_dot256(const float* __restrict__ Wrow,
                                             const float* __restrict__ x, int lane) {
    const float4* w4 = reinterpret_cast<const float4*>(Wrow);
    const float4* x4 = reinterpret_cast<const float4*>(x);
    float4 a0 = w4[lane],      b0 = x4[lane];
    float4 a1 = w4[lane + 32], b1 = x4[lane + 32];
    float s = a0.x * b0.x + a0.y * b0.y + a0.z * b0.z + a0.w * b0.w
            + a1.x * b1.x + a1.y * b1.y + a1.z * b1.z + a1.w * b1.w;
    return wredsum(s);
}

// ---------------------------------------------------------------------------
// Prolog A: sub = tanh(sub_W @ mask + sub_b).  warp-per-output.
// ---------------------------------------------------------------------------
__global__ void kA_sub(const float* __restrict__ mask, const float* __restrict__ sub_W,
                       const float* __restrict__ sub_b) {
    int lane = threadIdx.x & 31;
    int j = blockIdx.x * 8 + (threadIdx.x >> 5);
    float s = warp_dot256(sub_W + (size_t)j * D, mask, lane);
    if (lane == 0) g_sub[j] = tanhf(s + sub_b[j]);
}

// ---------------------------------------------------------------------------
// Prolog B: r0 = GRUCell(x=enc, h=sub).  warp-per-output.
// ---------------------------------------------------------------------------
__global__ void kB_r0(const float* __restrict__ enc, const float* __restrict__ W_ih,
                      const float* __restrict__ W_hh, const float* __restrict__ b_ih,
                      const float* __restrict__ b_hh) {
    int lane = threadIdx.x & 31;
    int j = blockIdx.x * 8 + (threadIdx.x >> 5);
    float gi[3], gh[3];
#pragma unroll
    for (int g = 0; g < 3; g++) {
        int row = g * D + j;
        gi[g] = warp_dot256(W_ih + (size_t)row * D, enc, lane);
        gh[g] = warp_dot256(W_hh + (size_t)row * D, g_sub, lane);
    }
    if (lane == 0) {
        float rg = sigmoidf_(gi[0] + b_ih[j] + gh[0] + b_hh[j]);
        float zg = sigmoidf_(gi[1] + b_ih[D + j] + gh[1] + b_hh[D + j]);
        float ng = tanhf(gi[2] + b_ih[2 * D + j] + rg * (gh[2] + b_hh[2 * D + j]));
        g_r0[j] = (1.0f - zg) * ng + zg * g_sub[j];
    }
}

// ---------------------------------------------------------------------------
// Prolog C: g_gi = W_ih @ r0 + b_ih  (768 outputs, shared by all edges).
// ---------------------------------------------------------------------------
__global__ void kC_gi(const float* __restrict__ W_ih, const float* __restrict__ b_ih) {
    int lane = threadIdx.x & 31;
    int j = blockIdx.x * 8 + (threadIdx.x >> 5);   // 0..767
    float s = warp_dot256(W_ih + (size_t)j * D, g_r0, lane);
    if (lane == 0) g_gi[j] = s + b_ih[j];
}

// ---------------------------------------------------------------------------
// k_rel v3: per-relation GRU + obj projection with COALESCED smem-staged W.
//   - stage k-tiles of all 3 gate matrices into smem (coalesced LDG.128,
//     conflict-free STS.128 via PAD=36 row stride)
//   - compute with conflict-free LDS.128 + packed f32x2 FMA over k-pairs
// Block: 256 threads, RT=8 relations; thread t owns output dim t of 3 gates.
// ---------------------------------------------------------------------------
__global__ void __launch_bounds__(256, 1)
k_rel(const float* __restrict__ rel_table, const float* __restrict__ W_hh,
      const float* __restrict__ b_hh, const float* __restrict__ obj_W,
      const float* __restrict__ obj_b, int R) {
    extern __shared__ float sm[];
    float* sW   = sm;                        // 3 * D * PAD floats
    float* s_h  = sm + 3 * D * PAD;          // RT * D
    float* s_rj = s_h + RT * D;              // RT * D

    int t = threadIdx.x;
    int rbase = blockIdx.x * RT;

#pragma unroll
    for (int r = 0; r < RT; r++)
        s_h[r * D + t] = (rbase + r < R) ? rel_table[(size_t)(rbase + r) * D + t] : 0.0f;

    u64 accR[RT], accZ[RT], accN[RT];
#pragma unroll
    for (int r = 0; r < RT; r++) { accR[r] = 0; accZ[r] = 0; accN[r] = 0; }

    // ---- gate phase: dot(W_hh[g*D + t], h[r]) for g=0..2, r=0..RT-1 ----
    for (int tile = 0; tile < NTILE; tile++) {
        __syncthreads();
        // stage 768 rows x KT cols, coalesced
#pragma unroll
        for (int i = 0; i < (3 * D * KT / 4) / 256; i++) {   // 24 float4 per thread
            int lin = (i * 256 + t) * 4;
            int row = lin / KT;           // 0..767
            int k   = lin % KT;
            float4 v = *reinterpret_cast<const float4*>(
                &W_hh[(size_t)row * D + tile * KT + k]);
            *reinterpret_cast<float4*>(&sW[row * PAD + k]) = v;
        }
        __syncthreads();
#pragma unroll
        for (int kk = 0; kk < KT; kk += 4) {
            int kg = tile * KT + kk;
            ulonglong2 h2[RT];
#pragma unroll
            for (int r = 0; r < RT; r++)
                h2[r] = *reinterpret_cast<const ulonglong2*>(&s_h[r * D + kg]);
            ulonglong2 wr = *reinterpret_cast<const ulonglong2*>(&sW[(0 * D + t) * PAD + kk]);
            ulonglong2 wz = *reinterpret_cast<const ulonglong2*>(&sW[(1 * D + t) * PAD + kk]);
            ulonglong2 wn = *reinterpret_cast<const ulonglong2*>(&sW[(2 * D + t) * PAD + kk]);
#pragma unroll
            for (int r = 0; r < RT; r++) {
                fma2(accR[r], wr.x, h2[r].x); fma2(accR[r], wr.y, h2[r].y);
                fma2(accZ[r], wz.x, h2[r].x); fma2(accZ[r], wz.y, h2[r].y);
                fma2(accN[r], wn.x, h2[r].x); fma2(accN[r], wn.y, h2[r].y);
            }
        }
    }

    // ---- GRU combine -> s_rj ----
    float ir = g_gi[t], iz = g_gi[D + t], in_ = g_gi[2 * D + t];
    float bhr = b_hh[t], bhz = b_hh[D + t], bhn = b_hh[2 * D + t];
#pragma unroll
    for (int r = 0; r < RT; r++) {
        float rg = sigmoidf_(ir + unpack_sum(accR[r]) + bhr);
        float zg = sigmoidf_(iz + unpack_sum(accZ[r]) + bhz);
        float ng = tanhf(in_ + rg * (unpack_sum(accN[r]) + bhn));
        s_rj[r * D + t] = (1.0f - zg) * ng + zg * s_h[r * D + t];
    }

    // ---- obj phase: tanh(obj_W @ rj + obj_b) ----
    u64 accO[RT];
#pragma unroll
    for (int r = 0; r < RT; r++) accO[r] = 0;

    for (int tile = 0; tile < NTILE; tile++) {
        __syncthreads();   // also orders s_rj writes before reads below
#pragma unroll
        for (int i = 0; i < (D * KT / 4) / 256; i++) {       // 8 float4 per thread
            int lin = (i * 256 + t) * 4;
            int row = lin / KT;           // 0..255
            int k   = lin % KT;
            float4 v = *reinterpret_cast<const float4*>(
                &obj_W[(size_t)row * D + tile * KT + k]);
            *reinterpret_cast<float4*>(&sW[row * PAD + k]) = v;
        }
        __syncthreads();
#pragma unroll
        for (int kk = 0; kk < KT; kk += 4) {
            int kg = tile * KT + kk;
            ulonglong2 wo = *reinterpret_cast<const ulonglong2*>(&sW[t * PAD + kk]);
#pragma unroll
            for (int r = 0; r < RT; r++) {
                ulonglong2 h2 = *reinterpret_cast<const ulonglong2*>(&s_rj[r * D + kg]);
                fma2(accO[r], wo.x, h2.x); fma2(accO[r], wo.y, h2.y);
            }
        }
    }

    float ob = obj_b[t];
#pragma unroll
    for (int r = 0; r < RT; r++) {
        if (rbase + r < R)
            g_obj[(size_t)(rbase + r) * D + t] = tanhf(unpack_sum(accO[r]) + ob);
    }
}

// ---------------------------------------------------------------------------
// Seed row (before tail scatter; tails override seed like the reference).
// ---------------------------------------------------------------------------
__global__ void k_seed(const int* __restrict__ seed_p, float* __restrict__ out) {
    int t = threadIdx.x;
    int seed = *seed_p;
    out[(size_t)seed * D + t] = g_sub[t];
}

// ---------------------------------------------------------------------------
// HBM-bound scatter, high MLP: warp handles 4 rows, lane copies 2 float4/row;
// all 8 loads issued before any store.
// ---------------------------------------------------------------------------
__global__ void k_scatter(const float* __restrict__ ent_table, const int* __restrict__ rel_ids,
                          const int* __restrict__ tail_ids, const int* __restrict__ tails_state,
                          const int* __restrict__ origin_ids, float* __restrict__ out, int E) {
    int warp = threadIdx.x >> 5;
    int lane = threadIdx.x & 31;
    int base = (blockIdx.x * 8 + warp) * 4;

    float4 v[4][2];
    float4* dst[4];
    bool ok[4];
#pragma unroll
    for (int i = 0; i < 4; i++) {
        int row = base + i;
        ok[i] = row < E;
        if (ok[i]) {
            int st = tails_state[row];
            const float4* src = (st == 1)
                ? reinterpret_cast<const float4*>(ent_table) + (size_t)origin_ids[row] * (D / 4)
                : reinterpret_cast<const float4*>(g_obj) + (size_t)rel_ids[row] * (D / 4);
            dst[i] = reinterpret_cast<float4*>(out) + (size_t)tail_ids[row] * (D / 4);
            v[i][0] = src[lane];
            v[i][1] = src[lane + 32];
        }
    }
#pragma unroll
    for (int i = 0; i < 4; i++) {
        if (ok[i]) {
            dst[i][lane] = v[i][0];
            dst[i][lane + 32] = v[i][1];
        }
    }
}

// ---------------------------------------------------------------------------
extern "C" void kernel_launch(void* const* d_in, const int* in_sizes, int n_in,
                              void* d_out, int out_size) {
    const float* enc       = (const float*)d_in[0];
    const float* mask      = (const float*)d_in[1];
    const float* ent_table = (const float*)d_in[2];
    const float* rel_table = (const float*)d_in[3];
    const float* W_ih      = (const float*)d_in[4];
    const float* W_hh      = (const float*)d_in[5];
    const float* b_ih      = (const float*)d_in[6];
    const float* b_hh      = (const float*)d_in[7];
    const float* sub_W     = (const float*)d_in[8];
    const float* sub_b     = (const float*)d_in[9];
    const float* obj_W     = (const float*)d_in[10];
    const float* obj_b     = (const float*)d_in[11];
    const int*   rel_ids   = (const int*)d_in[12];
    const int*   tail_ids  = (const int*)d_in[13];
    const int*   tails_st  = (const int*)d_in[14];
    const int*   origin    = (const int*)d_in[15];
    const int*   seed_p    = (const int*)d_in[16];
    float* out = (float*)d_out;

    int E = in_sizes[12];
    int R = in_sizes[3] / D;

    const int relSmem = (3 * D * PAD + 2 * RT * D) * 4;   // 126976 bytes
    cudaFuncSetAttribute(k_rel, cudaFuncAttributeMaxDynamicSharedMemorySize, relSmem);

    kA_sub<<<32, 256>>>(mask, sub_W, sub_b);
    kB_r0<<<32, 256>>>(enc, W_ih, W_hh, b_ih, b_hh);
    kC_gi<<<96, 256>>>(W_ih, b_ih);
    k_rel<<<(R + RT - 1) / RT, 256, relSmem>>>(rel_table, W_hh, b_hh, obj_W, obj_b, R);
    k_seed<<<1, D>>>(seed_p, out);
    k_scatter<<<(E + 31) / 32, 256>>>(ent_table, rel_ids, tail_ids, tails_st, origin, out, E);
}